// round 5
// baseline (speedup 1.0000x reference)
#include <cuda_runtime.h>
#include <cuda_bf16.h>
#include <cstdint>

// ---------------------------------------------------------------------------
// SemanticLSTM: B=256, T=80, E=512, I=H=1024, L=300, F=2048, V=32000
// Recurrence fully fused into ONE persistent kernel (128 CTAs, software grid
// barriers). GEMMs on tensor cores via base-ISA mma.sync bf16 with bf16x3
// split (hi*hi + hi*lo + lo*hi), fp32 accumulate.
// R5 fix: load_stage now fills the FULL 128-byte K-rows (R4 half-loaded smem).
// ---------------------------------------------------------------------------

#define BB 256
#define TT 80
#define EE 512
#define II 1024
#define HH 1024
#define LL 300
#define FF 2048

// fp32 scratch
__device__ float g_emb [BB * EE];
__device__ float g_bufA[BB * 4 * II];
__device__ float g_bufB[BB * 4 * II];
__device__ float g_base[BB * 4 * HH];
__device__ float g_SH  [BB * 4 * II];
__device__ float g_pre [BB * 4 * HH];
__device__ float g_c   [BB * HH];

// bf16 split buffers
__device__ __nv_bfloat16 g_hH[BB * HH];
__device__ __nv_bfloat16 g_hL[BB * HH];
__device__ __nv_bfloat16 g_xH[BB * 4 * II];
__device__ __nv_bfloat16 g_xL[BB * 4 * II];
// transposed split weights: UaT[g,i,h] = Ua[g,h,i]; UcT[g,h,i] = Uc[g,i,h]
__device__ __nv_bfloat16 g_UaT_h[4 * 1024 * 1024];
__device__ __nv_bfloat16 g_UaT_l[4 * 1024 * 1024];
__device__ __nv_bfloat16 g_UcT_h[4 * 1024 * 1024];
__device__ __nv_bfloat16 g_UcT_l[4 * 1024 * 1024];

// grid barrier counter (monotonic within a launch; reset by zero kernel)
__device__ unsigned g_bar;

// ---------------------------------------------------------------------------
// helpers (base-ISA: cp.async sm_80+, ldmatrix sm_75+, mma.sync sm_80+)
// ---------------------------------------------------------------------------
__device__ __forceinline__ uint32_t smem_u32(const void* p) {
    uint32_t a;
    asm("{ .reg .u64 t; cvta.to.shared.u64 t, %1; cvt.u32.u64 %0, t; }" : "=r"(a) : "l"(p));
    return a;
}
__device__ __forceinline__ void cpa16(uint32_t d, const void* s) {
    asm volatile("cp.async.cg.shared.global [%0], [%1], 16;" :: "r"(d), "l"(s));
}
__device__ __forceinline__ void cpa_commit() { asm volatile("cp.async.commit_group;"); }
template <int N>
__device__ __forceinline__ void cpa_wait() {
    asm volatile("cp.async.wait_group %0;" :: "n"(N) : "memory");
}
__device__ __forceinline__ void ldm_x4(uint32_t* r, uint32_t a) {
    asm volatile("ldmatrix.sync.aligned.m8n8.x4.shared.b16 {%0,%1,%2,%3}, [%4];"
                 : "=r"(r[0]), "=r"(r[1]), "=r"(r[2]), "=r"(r[3]) : "r"(a));
}
__device__ __forceinline__ void mma16816(float* d, const uint32_t* a, uint32_t b0, uint32_t b1) {
    asm volatile(
        "mma.sync.aligned.m16n8k16.row.col.f32.bf16.bf16.f32 "
        "{%0,%1,%2,%3},{%4,%5,%6,%7},{%8,%9},{%0,%1,%2,%3};"
        : "+f"(d[0]), "+f"(d[1]), "+f"(d[2]), "+f"(d[3])
        : "r"(a[0]), "r"(a[1]), "r"(a[2]), "r"(a[3]), "r"(b0), "r"(b1));
}

// software grid barrier (all 128 CTAs co-resident: 1 CTA/SM, 128 <= 148 SMs)
__device__ __forceinline__ void grid_sync(unsigned target) {
    __syncthreads();
    if (threadIdx.x == 0) {
        __threadfence();
        atomicAdd(&g_bar, 1u);
        while (*(volatile unsigned*)&g_bar < target) __nanosleep(32);
        __threadfence();
    }
    __syncthreads();
}

// ---------------------------------------------------------------------------
// zero state + barrier reset
// ---------------------------------------------------------------------------
__global__ __launch_bounds__(256) void zero_hc_kernel() {
    int idx = blockIdx.x * 256 + threadIdx.x;
    if (idx == 0) g_bar = 0;
    if (idx < BB * HH) {
        g_c[idx] = 0.f;
        g_hH[idx] = __float2bfloat16(0.f);
        g_hL[idx] = __float2bfloat16(0.f);
    }
}

// ---------------------------------------------------------------------------
// gather emb = embed[captions[:,0]]  (int64/int32 robust)
// ---------------------------------------------------------------------------
__global__ __launch_bounds__(256) void gather_emb_kernel(const void* __restrict__ caps,
                                                         const float* __restrict__ embed) {
    __shared__ int is64;
    if (threadIdx.x == 0) {
        const int* p = (const int*)caps;
        int z = 1;
        for (int k = 0; k < 16; k++)
            if (p[2 * k + 1] != 0) z = 0;
        is64 = z;
    }
    __syncthreads();
    int idx = blockIdx.x * 256 + threadIdx.x;
    if (idx >= BB * (EE / 4)) return;
    int b  = idx / (EE / 4);
    int e4 = idx % (EE / 4);
    long long cap;
    if (is64) cap = ((const long long*)caps)[(long long)b * TT];
    else      cap = (long long)((const int*)caps)[b * TT];
    float4 v = ((const float4*)embed)[cap * (EE / 4) + e4];
    ((float4*)g_emb)[idx] = v;
}

// ---------------------------------------------------------------------------
// transpose + bf16 split: dst[g,a,b] = split(src[g,b,a]); grid (32,32,4)
// ---------------------------------------------------------------------------
__global__ __launch_bounds__(256) void convT_kernel(const float* __restrict__ src,
                                                    __nv_bfloat16* __restrict__ dh,
                                                    __nv_bfloat16* __restrict__ dl) {
    __shared__ float t[32][33];
    int g  = blockIdx.z;
    int x0 = blockIdx.x * 32;
    int y0 = blockIdx.y * 32;
    int tx = threadIdx.x & 31, ty = threadIdx.x >> 5;
    const float* s = src + (size_t)g * 1048576;
#pragma unroll
    for (int k = 0; k < 4; k++)
        t[ty + k * 8][tx] = s[(size_t)(y0 + ty + k * 8) * 1024 + x0 + tx];
    __syncthreads();
    __nv_bfloat16* oh = dh + (size_t)g * 1048576;
    __nv_bfloat16* ol = dl + (size_t)g * 1048576;
#pragma unroll
    for (int k = 0; k < 4; k++) {
        float v = t[tx][ty + k * 8];
        size_t o = (size_t)(x0 + ty + k * 8) * 1024 + y0 + tx;
        __nv_bfloat16 hi = __float2bfloat16(v);
        oh[o] = hi;
        ol[o] = __float2bfloat16(v - __bfloat162float(hi));
    }
}

// ---------------------------------------------------------------------------
// fp32 prologue SGEMM (7 launches only)
// ---------------------------------------------------------------------------
#define BM 64
#define BN 128
#define BK 16

__global__ __launch_bounds__(256) void gemm4_kernel(
    const float* __restrict__ A, int lda, int agoff,
    const float* __restrict__ W, int K,
    const float* Z, const float* __restrict__ bias,
    float* C, int mode)
{
    const int N = 1024;
    const int g  = blockIdx.z;
    const int bx = blockIdx.x;
    const int by = blockIdx.y;

    __shared__ float As[BK][BM];
    __shared__ float Bs[BK][BN];

    const int tid = threadIdx.x;
    const int tx  = tid & 15;
    const int ty  = tid >> 4;

    const float* Ag = A + (size_t)g * agoff;
    const float* Wg = W + (size_t)g * K * N + bx * BN;

    float acc[4][8];
#pragma unroll
    for (int i = 0; i < 4; i++)
#pragma unroll
        for (int j = 0; j < 8; j++) acc[i][j] = 0.f;

    const int arow = tid >> 2;
    const int ac   = (tid & 3) * 4;

    for (int kk = 0; kk < K; kk += BK) {
        {
            const int m = by * BM + arow;
            const float* ap = Ag + (size_t)m * lda + kk + ac;
#pragma unroll
            for (int j = 0; j < 4; j++) {
                float v = (kk + ac + j < K) ? ap[j] : 0.f;
                As[ac + j][arow] = v;
            }
        }
#pragma unroll
        for (int r = 0; r < 2; r++) {
            int idx  = tid + r * 256;
            int brow = idx >> 5;
            int bc   = (idx & 31) * 4;
            int kg   = kk + brow;
            float4 v;
            if (kg < K) v = *(const float4*)(Wg + (size_t)kg * N + bc);
            else        v = make_float4(0.f, 0.f, 0.f, 0.f);
            *(float4*)&Bs[brow][bc] = v;
        }
        __syncthreads();

#pragma unroll
        for (int k = 0; k < BK; k++) {
            float4 av = *(const float4*)&As[k][ty * 4];
            float4 b0 = *(const float4*)&Bs[k][tx * 8];
            float4 b1 = *(const float4*)&Bs[k][tx * 8 + 4];
            float a[4] = {av.x, av.y, av.z, av.w};
            float b[8] = {b0.x, b0.y, b0.z, b0.w, b1.x, b1.y, b1.z, b1.w};
#pragma unroll
            for (int i = 0; i < 4; i++)
#pragma unroll
                for (int j = 0; j < 8; j++)
                    acc[i][j] = fmaf(a[i], b[j], acc[i][j]);
        }
        __syncthreads();
    }

#pragma unroll
    for (int i = 0; i < 4; i++) {
        const int m = by * BM + ty * 4 + i;
        const int n0 = bx * BN + tx * 8;
        size_t row = (size_t)m * 4096 + (size_t)g * 1024 + n0;
#pragma unroll
        for (int j = 0; j < 8; j++) {
            float v = acc[i][j];
            if (mode == 1)      v *= Z[row + j];
            else if (mode == 2) {
                v += Z[row + j];
                if (bias) v += bias[g * 1024 + n0 + j];
            }
            C[row + j] = v;
        }
    }
}

// ---------------------------------------------------------------------------
// Persistent recurrence kernel.
// 128 CTAs x 256 threads. CTA -> (g = cta&3, my = (cta>>2)&1, nx = cta>>3).
// GEMM tile per CTA: M=128 x N=64, K=1024 in 16 chunks of 64 (double buffer).
// 8 warps: wm = warp&3 (32 rows), wn = warp>>2 (32 cols).
// ---------------------------------------------------------------------------
#define ASTRIDE   144                    // bytes per smem row (64 bf16 + pad)
#define A_TILE_B  (128 * ASTRIDE)        // 18432
#define B_TILE_B  (64  * ASTRIDE)        // 9216
#define STAGE_B   (2 * A_TILE_B + 2 * B_TILE_B)  // 55296: Ah|Al|Bh|Bl
#define MM_SMEM   (2 * STAGE_B)          // 110592

__device__ __forceinline__ void load_stage(
    uint32_t s,
    const __nv_bfloat16* __restrict__ Ah, const __nv_bfloat16* __restrict__ Al, int lda,
    const __nv_bfloat16* __restrict__ Bh, const __nv_bfloat16* __restrict__ Bl,
    int k0, int tid)
{
    // A: 128 rows x 8 chunks of 16B (full 128-byte K-row) = 1024 cp.async
#pragma unroll
    for (int r = 0; r < 4; r++) {
        int id  = tid + (r << 8);
        int row = id >> 3;
        int cb  = id & 7;
        uint32_t d = s + row * ASTRIDE + cb * 16;
        size_t  sp = (size_t)row * lda + k0 + cb * 8;
        cpa16(d,            Ah + sp);
        cpa16(d + A_TILE_B, Al + sp);
    }
    // B: 64 rows x 8 chunks of 16B = 512 cp.async
#pragma unroll
    for (int r = 0; r < 2; r++) {
        int id  = tid + (r << 8);
        int row = id >> 3;
        int cb  = id & 7;
        uint32_t d = s + 2 * A_TILE_B + row * ASTRIDE + cb * 16;
        size_t  sp = (size_t)row * 1024 + k0 + cb * 8;
        cpa16(d,            Bh + sp);
        cpa16(d + B_TILE_B, Bl + sp);
    }
}

__device__ __forceinline__ void gemm_phase(
    uint32_t sbase, int tid,
    const __nv_bfloat16* __restrict__ Ah, const __nv_bfloat16* __restrict__ Al, int lda,
    const __nv_bfloat16* __restrict__ Bh, const __nv_bfloat16* __restrict__ Bl,
    int m_base, int n_col,
    const float* __restrict__ Z,
    float* __restrict__ outF, __nv_bfloat16* __restrict__ outH, __nv_bfloat16* __restrict__ outL,
    int mode)
{
    const int lane = tid & 31;
    const int warp = tid >> 5;
    const int wm   = warp & 3;
    const int wn   = warp >> 2;

    float acc[2][4][4];
#pragma unroll
    for (int i = 0; i < 2; i++)
#pragma unroll
        for (int j = 0; j < 4; j++)
#pragma unroll
            for (int k = 0; k < 4; k++) acc[i][j][k] = 0.f;

    const int rin  = lane & 7;
    const int quad = lane >> 3;
    const uint32_t aoff = ((quad & 1) * 8 + rin) * ASTRIDE + (quad >> 1) * 16;
    const uint32_t boff = ((quad >> 1) * 8 + rin) * ASTRIDE + (quad & 1) * 16;

    load_stage(sbase, Ah, Al, lda, Bh, Bl, 0, tid);
    cpa_commit();

    for (int c = 0; c < 16; c++) {
        const uint32_t soff = (c & 1) * STAGE_B;
        if (c + 1 < 16) {
            load_stage(sbase + ((c + 1) & 1) * STAGE_B, Ah, Al, lda, Bh, Bl, (c + 1) * 64, tid);
            cpa_commit();
            cpa_wait<1>();
        } else {
            cpa_wait<0>();
        }
        __syncthreads();

        const uint32_t aCur = sbase + soff + wm * 32 * ASTRIDE + aoff;
        const uint32_t bCur = sbase + soff + 2 * A_TILE_B + wn * 32 * ASTRIDE + boff;
#pragma unroll
        for (int ks = 0; ks < 4; ks++) {
            uint32_t ah[2][4], al[2][4], bh[2][4], bl[2][4];
            const uint32_t ka = aCur + ks * 32;
            const uint32_t kb = bCur + ks * 32;
            ldm_x4(ah[0], ka);
            ldm_x4(ah[1], ka + 16 * ASTRIDE);
            ldm_x4(al[0], ka + A_TILE_B);
            ldm_x4(al[1], ka + A_TILE_B + 16 * ASTRIDE);
            ldm_x4(bh[0], kb);
            ldm_x4(bh[1], kb + 16 * ASTRIDE);
            ldm_x4(bl[0], kb + B_TILE_B);
            ldm_x4(bl[1], kb + B_TILE_B + 16 * ASTRIDE);
#pragma unroll
            for (int im = 0; im < 2; im++)
#pragma unroll
                for (int jn = 0; jn < 4; jn++) {
                    const int jp = jn >> 1, q = (jn & 1) * 2;
                    mma16816(acc[im][jn], ah[im], bh[jp][q], bh[jp][q + 1]);
                    mma16816(acc[im][jn], ah[im], bl[jp][q], bl[jp][q + 1]);
                    mma16816(acc[im][jn], al[im], bh[jp][q], bh[jp][q + 1]);
                }
        }
        __syncthreads();
    }

#pragma unroll
    for (int im = 0; im < 2; im++) {
        const int m0 = m_base + wm * 32 + im * 16 + (lane >> 2);
#pragma unroll
        for (int jn = 0; jn < 4; jn++) {
            const int n0 = n_col + wn * 32 + jn * 8 + (lane & 3) * 2;
            const size_t p0 = (size_t)m0 * 4096 + n0;
            const size_t p1 = p0 + 8 * 4096;
            const float* a = acc[im][jn];
            if (mode == 1) {
                float x0 = a[0] * Z[p0],  x1 = a[1] * Z[p0 + 1];
                float x2 = a[2] * Z[p1],  x3 = a[3] * Z[p1 + 1];
                __nv_bfloat16 h0 = __float2bfloat16(x0);
                __nv_bfloat16 h1 = __float2bfloat16(x1);
                __nv_bfloat16 h2 = __float2bfloat16(x2);
                __nv_bfloat16 h3 = __float2bfloat16(x3);
                outH[p0] = h0; outH[p0 + 1] = h1;
                outH[p1] = h2; outH[p1 + 1] = h3;
                outL[p0]     = __float2bfloat16(x0 - __bfloat162float(h0));
                outL[p0 + 1] = __float2bfloat16(x1 - __bfloat162float(h1));
                outL[p1]     = __float2bfloat16(x2 - __bfloat162float(h2));
                outL[p1 + 1] = __float2bfloat16(x3 - __bfloat162float(h3));
            } else {
                outF[p0]     = a[0] + Z[p0];
                outF[p0 + 1] = a[1] + Z[p0 + 1];
                outF[p1]     = a[2] + Z[p1];
                outF[p1 + 1] = a[3] + Z[p1 + 1];
            }
        }
    }
}

__device__ __forceinline__ float gate1(float xi, float xf, float xo, float xg, float& c) {
    float ig = 1.f / (1.f + expf(-xi));
    float fg = 1.f / (1.f + expf(-xf));
    float og = 1.f / (1.f + expf(-xo));
    float gg = tanhf(xg);
    c = fg * c + ig * gg;
    return og * tanhf(c);
}

__device__ __forceinline__ void gate_phase(int cta, int tid, float* out) {
    const int idx = cta * 2048 + tid * 8;
    const int b = idx >> 10, h0 = idx & 1023;
    const float* pp = g_pre + ((size_t)b << 12) + h0;
#pragma unroll
    for (int q = 0; q < 2; q++) {
        float4 xi = __ldcg((const float4*)(pp + q * 4));
        float4 xf = __ldcg((const float4*)(pp + 1024 + q * 4));
        float4 xo = __ldcg((const float4*)(pp + 2048 + q * 4));
        float4 xg = __ldcg((const float4*)(pp + 3072 + q * 4));
        float4 cc = *(const float4*)&g_c[idx + q * 4];
        float hv0 = gate1(xi.x, xf.x, xo.x, xg.x, cc.x);
        float hv1 = gate1(xi.y, xf.y, xo.y, xg.y, cc.y);
        float hv2 = gate1(xi.z, xf.z, xo.z, xg.z, cc.z);
        float hv3 = gate1(xi.w, xf.w, xo.w, xg.w, cc.w);
        *(float4*)&g_c[idx + q * 4] = cc;
        __nv_bfloat16 b0 = __float2bfloat16(hv0);
        __nv_bfloat16 b1 = __float2bfloat16(hv1);
        __nv_bfloat16 b2 = __float2bfloat16(hv2);
        __nv_bfloat16 b3 = __float2bfloat16(hv3);
        *(__nv_bfloat162*)&g_hH[idx + q * 4]     = __nv_bfloat162{b0, b1};
        *(__nv_bfloat162*)&g_hH[idx + q * 4 + 2] = __nv_bfloat162{b2, b3};
        *(__nv_bfloat162*)&g_hL[idx + q * 4] =
            __nv_bfloat162{__float2bfloat16(hv0 - __bfloat162float(b0)),
                           __float2bfloat16(hv1 - __bfloat162float(b1))};
        *(__nv_bfloat162*)&g_hL[idx + q * 4 + 2] =
            __nv_bfloat162{__float2bfloat16(hv2 - __bfloat162float(b2)),
                           __float2bfloat16(hv3 - __bfloat162float(b3))};
        if (out) *(float4*)&out[idx + q * 4] = make_float4(hv0, hv1, hv2, hv3);
    }
}

__global__ __launch_bounds__(256, 1) void lstm_persist_kernel(
    const __nv_bfloat16* __restrict__ UaTh, const __nv_bfloat16* __restrict__ UaTl,
    const __nv_bfloat16* __restrict__ UcTh, const __nv_bfloat16* __restrict__ UcTl,
    float* __restrict__ out)
{
    extern __shared__ char dsm[];
    const uint32_t sbase = smem_u32(dsm);
    const int cta = blockIdx.x;
    const int tid = threadIdx.x;
    const int g   = cta & 3;
    const int my  = (cta >> 2) & 1;
    const int nx  = cta >> 3;

    const int m_base = my * 128;
    const int n_col  = g * 1024 + nx * 64;

    const __nv_bfloat16* A1h = g_hH + (size_t)m_base * 1024;
    const __nv_bfloat16* A1l = g_hL + (size_t)m_base * 1024;
    const __nv_bfloat16* B1h = UaTh + ((size_t)g << 20) + (size_t)(nx * 64) * 1024;
    const __nv_bfloat16* B1l = UaTl + ((size_t)g << 20) + (size_t)(nx * 64) * 1024;
    const __nv_bfloat16* A2h = g_xH + (size_t)m_base * 4096 + (size_t)g * 1024;
    const __nv_bfloat16* A2l = g_xL + (size_t)m_base * 4096 + (size_t)g * 1024;
    const __nv_bfloat16* B2h = UcTh + ((size_t)g << 20) + (size_t)(nx * 64) * 1024;
    const __nv_bfloat16* B2l = UcTl + ((size_t)g << 20) + (size_t)(nx * 64) * 1024;

    unsigned sync_no = 0;
    for (int t = 0; t < TT; t++) {
        // X = (h @ UaT) * SH -> bf16 hi/lo
        gemm_phase(sbase, tid, A1h, A1l, 1024, B1h, B1l,
                   m_base, n_col, g_SH, nullptr, g_xH, g_xL, 1);
        grid_sync(++sync_no * 128u);
        // pre = (X @ UcT) + base -> fp32
        gemm_phase(sbase, tid, A2h, A2l, 4096, B2h, B2l,
                   m_base, n_col, g_base, g_pre, nullptr, nullptr, 2);
        grid_sync(++sync_no * 128u);
        gate_phase(cta, tid, (t == TT - 1) ? out : nullptr);
        grid_sync(++sync_no * 128u);
    }
}

// ---------------------------------------------------------------------------
extern "C" void kernel_launch(void* const* d_in, const int* in_sizes, int n_in,
                              void* d_out, int out_size) {
    const void*  caps  = d_in[0];
    const float* cnn   = (const float*)d_in[1];
    const float* sem   = (const float*)d_in[2];
    const float* embed = (const float*)d_in[3];
    const float* Wa    = (const float*)d_in[4];
    const float* Wb    = (const float*)d_in[5];
    const float* Wc    = (const float*)d_in[6];
    const float* Ua    = (const float*)d_in[7];
    const float* Ub    = (const float*)d_in[8];
    const float* Uc    = (const float*)d_in[9];
    const float* Ca    = (const float*)d_in[10];
    const float* Cb    = (const float*)d_in[11];
    const float* Cc    = (const float*)d_in[12];
    const float* bias  = (const float*)d_in[13];

    float *p_emb, *p_bufA, *p_bufB, *p_base, *p_SH;
    cudaGetSymbolAddress((void**)&p_emb,  g_emb);
    cudaGetSymbolAddress((void**)&p_bufA, g_bufA);
    cudaGetSymbolAddress((void**)&p_bufB, g_bufB);
    cudaGetSymbolAddress((void**)&p_base, g_base);
    cudaGetSymbolAddress((void**)&p_SH,   g_SH);

    __nv_bfloat16 *p_UaTh, *p_UaTl, *p_UcTh, *p_UcTl;
    cudaGetSymbolAddress((void**)&p_UaTh, g_UaT_h);
    cudaGetSymbolAddress((void**)&p_UaTl, g_UaT_l);
    cudaGetSymbolAddress((void**)&p_UcTh, g_UcT_h);
    cudaGetSymbolAddress((void**)&p_UcTl, g_UcT_l);

    cudaFuncSetAttribute(lstm_persist_kernel, cudaFuncAttributeMaxDynamicSharedMemorySize, MM_SMEM);

    dim3 gg(1024 / BN, BB / BM, 4);   // prologue fp32 GEMM grid
    dim3 cg(32, 32, 4);               // weight conversion grid

    zero_hc_kernel<<<(BB * HH + 255) / 256, 256>>>();
    gather_emb_kernel<<<(BB * EE / 4 + 255) / 256, 256>>>(caps, embed);
    convT_kernel<<<cg, 256>>>(Ua, p_UaTh, p_UaTl);
    convT_kernel<<<cg, 256>>>(Uc, p_UcTh, p_UcTl);

    // base = (emb@Wa * sem@Wb)@Wc + (cnn@Ca * sem@Cb)@Cc + bias ; SH = sem@Ub
    gemm4_kernel<<<gg, 256>>>(p_emb,  EE,   0,    Wa, EE, nullptr, nullptr, p_bufA, 0);
    gemm4_kernel<<<gg, 256>>>(sem,    LL,   0,    Wb, LL, p_bufA,  nullptr, p_bufB, 1);
    gemm4_kernel<<<gg, 256>>>(p_bufB, 4096, 1024, Wc, II, nullptr, nullptr, p_base, 0);
    gemm4_kernel<<<gg, 256>>>(cnn,    FF,   0,    Ca, FF, nullptr, nullptr, p_bufA, 0);
    gemm4_kernel<<<gg, 256>>>(sem,    LL,   0,    Cb, LL, p_bufA,  nullptr, p_bufB, 1);
    gemm4_kernel<<<gg, 256>>>(p_bufB, 4096, 1024, Cc, II, p_base,  bias,    p_base, 2);
    gemm4_kernel<<<gg, 256>>>(sem,    LL,   0,    Ub, LL, nullptr, nullptr, p_SH,   0);

    // whole 80-step recurrence in one persistent kernel
    lstm_persist_kernel<<<128, 256, MM_SMEM>>>(p_UaTh, p_UaTl, p_UcTh, p_UcTl, (float*)d_out);
}

// round 6
// speedup vs baseline: 1.3313x; 1.3313x over previous
#include <cuda_runtime.h>
#include <cuda_fp16.h>
#include <cstdint>

// ---------------------------------------------------------------------------
// SemanticLSTM: B=256, T=80, E=512, I=H=1024, L=300, F=2048, V=32000
// Recurrence GEMMs on tensor cores via base-ISA mma.sync fp16 (sm_103 target
// has no tcgen05). fp16 2-pass: weights split W = Wh + Wl*2^-12 (exact to
// ~2^-23), activations single fp16 (err ~2^-12, damped by the recurrence).
// ---------------------------------------------------------------------------

#define BB 256
#define TT 80
#define EE 512
#define II 1024
#define HH 1024
#define LL 300
#define FF 2048

// fp32 scratch
__device__ float g_emb [BB * EE];
__device__ float g_bufA[BB * 4 * II];
__device__ float g_bufB[BB * 4 * II];
__device__ float g_base[BB * 4 * HH];
__device__ float g_SH  [BB * 4 * II];
__device__ float g_pre [BB * 4 * HH];
__device__ float g_c   [BB * HH];

// fp16 activation buffers (single precision-level: err 2^-12 is in budget)
__device__ __half g_h16[BB * HH];
__device__ __half g_x16[BB * 4 * II];
// transposed split weights: UaT[g,i,h] = Ua[g,h,i]; UcT[g,h,i] = Uc[g,i,h]
// lo term pre-scaled by 2^12 so it stays in fp16 normal range.
__device__ __half g_UaT_h[4 * 1024 * 1024];
__device__ __half g_UaT_l[4 * 1024 * 1024];
__device__ __half g_UcT_h[4 * 1024 * 1024];
__device__ __half g_UcT_l[4 * 1024 * 1024];

#define LO_SCALE    4096.0f
#define LO_INVSCALE 0.000244140625f   // 2^-12

// ---------------------------------------------------------------------------
// helpers (base-ISA: cp.async sm_80+, ldmatrix sm_75+, mma.sync sm_80+)
// ---------------------------------------------------------------------------
__device__ __forceinline__ uint32_t smem_u32(const void* p) {
    uint32_t a;
    asm("{ .reg .u64 t; cvta.to.shared.u64 t, %1; cvt.u32.u64 %0, t; }" : "=r"(a) : "l"(p));
    return a;
}
__device__ __forceinline__ void cpa16(uint32_t d, const void* s) {
    asm volatile("cp.async.cg.shared.global [%0], [%1], 16;" :: "r"(d), "l"(s));
}
__device__ __forceinline__ void cpa_commit() { asm volatile("cp.async.commit_group;"); }
template <int N>
__device__ __forceinline__ void cpa_wait() {
    asm volatile("cp.async.wait_group %0;" :: "n"(N) : "memory");
}
__device__ __forceinline__ void ldm_x4(uint32_t* r, uint32_t a) {
    asm volatile("ldmatrix.sync.aligned.m8n8.x4.shared.b16 {%0,%1,%2,%3}, [%4];"
                 : "=r"(r[0]), "=r"(r[1]), "=r"(r[2]), "=r"(r[3]) : "r"(a));
}
__device__ __forceinline__ void mma16816(float* d, const uint32_t* a, uint32_t b0, uint32_t b1) {
    asm volatile(
        "mma.sync.aligned.m16n8k16.row.col.f32.f16.f16.f32 "
        "{%0,%1,%2,%3},{%4,%5,%6,%7},{%8,%9},{%0,%1,%2,%3};"
        : "+f"(d[0]), "+f"(d[1]), "+f"(d[2]), "+f"(d[3])
        : "r"(a[0]), "r"(a[1]), "r"(a[2]), "r"(a[3]), "r"(b0), "r"(b1));
}

// ---------------------------------------------------------------------------
// zero state
// ---------------------------------------------------------------------------
__global__ __launch_bounds__(256) void zero_hc_kernel() {
    int idx = blockIdx.x * 256 + threadIdx.x;
    if (idx < BB * HH) {
        g_c[idx] = 0.f;
        g_h16[idx] = __float2half(0.f);
    }
}

// ---------------------------------------------------------------------------
// gather emb = embed[captions[:,0]]  (int64/int32 robust)
// ---------------------------------------------------------------------------
__global__ __launch_bounds__(256) void gather_emb_kernel(const void* __restrict__ caps,
                                                         const float* __restrict__ embed) {
    __shared__ int is64;
    if (threadIdx.x == 0) {
        const int* p = (const int*)caps;
        int z = 1;
        for (int k = 0; k < 16; k++)
            if (p[2 * k + 1] != 0) z = 0;
        is64 = z;
    }
    __syncthreads();
    int idx = blockIdx.x * 256 + threadIdx.x;
    if (idx >= BB * (EE / 4)) return;
    int b  = idx / (EE / 4);
    int e4 = idx % (EE / 4);
    long long cap;
    if (is64) cap = ((const long long*)caps)[(long long)b * TT];
    else      cap = (long long)((const int*)caps)[b * TT];
    float4 v = ((const float4*)embed)[cap * (EE / 4) + e4];
    ((float4*)g_emb)[idx] = v;
}

// ---------------------------------------------------------------------------
// transpose + fp16 split: dst[g,a,b] = split(src[g,b,a]); grid (32,32,4)
// dh = fp16(w); dl = fp16((w - dh) * 4096)
// ---------------------------------------------------------------------------
__global__ __launch_bounds__(256) void convT_kernel(const float* __restrict__ src,
                                                    __half* __restrict__ dh,
                                                    __half* __restrict__ dl) {
    __shared__ float t[32][33];
    int g  = blockIdx.z;
    int x0 = blockIdx.x * 32;
    int y0 = blockIdx.y * 32;
    int tx = threadIdx.x & 31, ty = threadIdx.x >> 5;
    const float* s = src + (size_t)g * 1048576;
#pragma unroll
    for (int k = 0; k < 4; k++)
        t[ty + k * 8][tx] = s[(size_t)(y0 + ty + k * 8) * 1024 + x0 + tx];
    __syncthreads();
    __half* oh = dh + (size_t)g * 1048576;
    __half* ol = dl + (size_t)g * 1048576;
#pragma unroll
    for (int k = 0; k < 4; k++) {
        float v = t[tx][ty + k * 8];
        size_t o = (size_t)(x0 + ty + k * 8) * 1024 + y0 + tx;
        __half hi = __float2half(v);
        oh[o] = hi;
        ol[o] = __float2half((v - __half2float(hi)) * LO_SCALE);
    }
}

// ---------------------------------------------------------------------------
// fp32 prologue SGEMM (7 launches only)
// ---------------------------------------------------------------------------
#define BM 64
#define BN 128
#define BK 16

__global__ __launch_bounds__(256) void gemm4_kernel(
    const float* __restrict__ A, int lda, int agoff,
    const float* __restrict__ W, int K,
    const float* Z, const float* __restrict__ bias,
    float* C, int mode)
{
    const int N = 1024;
    const int g  = blockIdx.z;
    const int bx = blockIdx.x;
    const int by = blockIdx.y;

    __shared__ float As[BK][BM];
    __shared__ float Bs[BK][BN];

    const int tid = threadIdx.x;
    const int tx  = tid & 15;
    const int ty  = tid >> 4;

    const float* Ag = A + (size_t)g * agoff;
    const float* Wg = W + (size_t)g * K * N + bx * BN;

    float acc[4][8];
#pragma unroll
    for (int i = 0; i < 4; i++)
#pragma unroll
        for (int j = 0; j < 8; j++) acc[i][j] = 0.f;

    const int arow = tid >> 2;
    const int ac   = (tid & 3) * 4;

    for (int kk = 0; kk < K; kk += BK) {
        {
            const int m = by * BM + arow;
            const float* ap = Ag + (size_t)m * lda + kk + ac;
#pragma unroll
            for (int j = 0; j < 4; j++) {
                float v = (kk + ac + j < K) ? ap[j] : 0.f;
                As[ac + j][arow] = v;
            }
        }
#pragma unroll
        for (int r = 0; r < 2; r++) {
            int idx  = tid + r * 256;
            int brow = idx >> 5;
            int bc   = (idx & 31) * 4;
            int kg   = kk + brow;
            float4 v;
            if (kg < K) v = *(const float4*)(Wg + (size_t)kg * N + bc);
            else        v = make_float4(0.f, 0.f, 0.f, 0.f);
            *(float4*)&Bs[brow][bc] = v;
        }
        __syncthreads();

#pragma unroll
        for (int k = 0; k < BK; k++) {
            float4 av = *(const float4*)&As[k][ty * 4];
            float4 b0 = *(const float4*)&Bs[k][tx * 8];
            float4 b1 = *(const float4*)&Bs[k][tx * 8 + 4];
            float a[4] = {av.x, av.y, av.z, av.w};
            float b[8] = {b0.x, b0.y, b0.z, b0.w, b1.x, b1.y, b1.z, b1.w};
#pragma unroll
            for (int i = 0; i < 4; i++)
#pragma unroll
                for (int j = 0; j < 8; j++)
                    acc[i][j] = fmaf(a[i], b[j], acc[i][j]);
        }
        __syncthreads();
    }

#pragma unroll
    for (int i = 0; i < 4; i++) {
        const int m = by * BM + ty * 4 + i;
        const int n0 = bx * BN + tx * 8;
        size_t row = (size_t)m * 4096 + (size_t)g * 1024 + n0;
#pragma unroll
        for (int j = 0; j < 8; j++) {
            float v = acc[i][j];
            if (mode == 1)      v *= Z[row + j];
            else if (mode == 2) {
                v += Z[row + j];
                if (bias) v += bias[g * 1024 + n0 + j];
            }
            C[row + j] = v;
        }
    }
}

// ---------------------------------------------------------------------------
// Tensor-core fp16 2-pass GEMM via mma.sync.m16n8k16.
// CTA tile M=64 x N=128, BK=64, K=1024 (16 chunks), double-buffered cp.async.
// grid (8 n-tiles, 4 m-tiles, 4 gates) = 128 CTAs, 256 threads (8 warps 32x32).
// acc = acc_hi + acc_lo * 2^-12
// mode 1: out = acc * Z -> fp16 ; mode 2: out = acc + Z -> fp32
// ---------------------------------------------------------------------------
#define ASTRIDE  144                     // bytes per smem row (64 fp16 + pad)
#define A_TILE_B (64  * ASTRIDE)         // 9216
#define B_TILE_B (128 * ASTRIDE)         // 18432 per split half
#define STAGE_B  (A_TILE_B + 2 * B_TILE_B)  // 46080: A | Bh | Bl
#define MM_SMEM  (2 * STAGE_B)           // 92160

__device__ __forceinline__ void load_stage(
    uint32_t sa, uint32_t sb,
    const __half* __restrict__ A, int lda,
    const __half* __restrict__ Bh, const __half* __restrict__ Bl,
    int k0, int tid)
{
    // A: 64 rows x 8 chunks of 16B = 512 cp.async
#pragma unroll
    for (int r = 0; r < 2; r++) {
        int id  = tid + (r << 8);
        int row = id >> 3;
        int cb  = id & 7;
        uint32_t d = sa + row * ASTRIDE + cb * 16;
        size_t  sp = (size_t)row * lda + k0 + cb * 8;
        cpa16(d, A + sp);
    }
    // B: 128 rows x 8 chunks of 16B, hi + lo = 2048 cp.async
#pragma unroll
    for (int r = 0; r < 4; r++) {
        int id  = tid + (r << 8);
        int row = id >> 3;
        int cb  = id & 7;
        uint32_t d = sb + row * ASTRIDE + cb * 16;
        size_t  sp = (size_t)row * 1024 + k0 + cb * 8;
        cpa16(d,            Bh + sp);
        cpa16(d + B_TILE_B, Bl + sp);
    }
}

__global__ __launch_bounds__(256, 1) void tcmma_kernel(
    const __half* __restrict__ A, int lda, int agoff,
    const __half* __restrict__ Bh, const __half* __restrict__ Bl,
    const float* __restrict__ Z,
    float* outF, __half* outH, int mode)
{
    extern __shared__ char dsm[];
    const uint32_t sbase = smem_u32(dsm);

    const int g    = blockIdx.z;
    const int nx   = blockIdx.x;   // 0..7 (128-wide n tile within gate)
    const int my   = blockIdx.y;   // 0..3 (64-wide m tile)
    const int tid  = threadIdx.x;
    const int lane = tid & 31;
    const int warp = tid >> 5;
    const int wm   = warp & 1;     // 0..1 -> 32 rows
    const int wn   = warp >> 1;    // 0..3 -> 32 cols

    const __half* Ap  = A + (size_t)g * agoff + (size_t)(my * 64) * lda;
    const __half* Bhp = Bh + ((size_t)g * 1024 + nx * 128) * 1024;
    const __half* Blp = Bl + ((size_t)g * 1024 + nx * 128) * 1024;

    float acc1[2][4][4], acc2[2][4][4];
#pragma unroll
    for (int i = 0; i < 2; i++)
#pragma unroll
        for (int j = 0; j < 4; j++)
#pragma unroll
            for (int k = 0; k < 4; k++) { acc1[i][j][k] = 0.f; acc2[i][j][k] = 0.f; }

    // per-lane ldmatrix base offsets
    const int rin  = lane & 7;
    const int quad = lane >> 3;
    const uint32_t aoff = ((quad & 1) * 8 + rin) * ASTRIDE + (quad >> 1) * 16;
    const uint32_t boff = ((quad >> 1) * 8 + rin) * ASTRIDE + (quad & 1) * 16;
    const uint32_t aBase = sbase + wm * 32 * ASTRIDE + aoff;
    const uint32_t bBase = sbase + A_TILE_B + wn * 32 * ASTRIDE + boff;

    // preload chunk 0
    load_stage(sbase, sbase + A_TILE_B, Ap, lda, Bhp, Blp, 0, tid);
    cpa_commit();

    const int NC = 16;
    for (int c = 0; c < NC; c++) {
        const uint32_t soff = (c & 1) * STAGE_B;
        if (c + 1 < NC) {
            const uint32_t s2 = ((c + 1) & 1) * STAGE_B;
            load_stage(sbase + s2, sbase + s2 + A_TILE_B, Ap, lda, Bhp, Blp, (c + 1) * 64, tid);
            cpa_commit();
            cpa_wait<1>();
        } else {
            cpa_wait<0>();
        }
        __syncthreads();

        const uint32_t aCur = aBase + soff;
        const uint32_t bCur = bBase + soff;
#pragma unroll
        for (int ks = 0; ks < 4; ks++) {
            uint32_t a[2][4], bh[2][4], bl[2][4];
            const uint32_t ka = aCur + ks * 32;
            const uint32_t kb = bCur + ks * 32;
            ldm_x4(a[0], ka);
            ldm_x4(a[1], ka + 16 * ASTRIDE);
            ldm_x4(bh[0], kb);
            ldm_x4(bh[1], kb + 16 * ASTRIDE);
            ldm_x4(bl[0], kb + B_TILE_B);
            ldm_x4(bl[1], kb + B_TILE_B + 16 * ASTRIDE);
#pragma unroll
            for (int im = 0; im < 2; im++)
#pragma unroll
                for (int jn = 0; jn < 4; jn++) {
                    const int jp = jn >> 1, q = (jn & 1) * 2;
                    mma16816(acc1[im][jn], a[im], bh[jp][q], bh[jp][q + 1]);
                    mma16816(acc2[im][jn], a[im], bl[jp][q], bl[jp][q + 1]);
                }
        }
        __syncthreads();
    }

    // epilogue: acc = acc1 + acc2 * 2^-12
#pragma unroll
    for (int im = 0; im < 2; im++) {
        const int m0 = my * 64 + wm * 32 + im * 16 + (lane >> 2);
#pragma unroll
        for (int jn = 0; jn < 4; jn++) {
            const int n0 = nx * 128 + wn * 32 + jn * 8 + (lane & 3) * 2;
            const size_t p0 = (size_t)m0 * 4096 + (size_t)g * 1024 + n0;
            const size_t p1 = p0 + 8 * 4096;   // m0 + 8
            const float* a1 = acc1[im][jn];
            const float* a2 = acc2[im][jn];
            float d0 = fmaf(a2[0], LO_INVSCALE, a1[0]);
            float d1 = fmaf(a2[1], LO_INVSCALE, a1[1]);
            float d2 = fmaf(a2[2], LO_INVSCALE, a1[2]);
            float d3 = fmaf(a2[3], LO_INVSCALE, a1[3]);
            if (mode == 1) {
                __half2 h01 = __floats2half2_rn(d0 * Z[p0], d1 * Z[p0 + 1]);
                __half2 h23 = __floats2half2_rn(d2 * Z[p1], d3 * Z[p1 + 1]);
                *(__half2*)&outH[p0] = h01;
                *(__half2*)&outH[p1] = h23;
            } else {
                outF[p0]     = d0 + Z[p0];
                outF[p0 + 1] = d1 + Z[p0 + 1];
                outF[p1]     = d2 + Z[p1];
                outF[p1 + 1] = d3 + Z[p1 + 1];
            }
        }
    }
}

// ---------------------------------------------------------------------------
// LSTM gate update: reads g_pre, updates g_c, writes h as fp16
// ---------------------------------------------------------------------------
__global__ __launch_bounds__(256) void lstm_gate_kernel(float* out) {
    int idx = blockIdx.x * 256 + threadIdx.x;
    if (idx >= BB * HH) return;
    int b  = idx >> 10;
    int hh = idx & 1023;
    const float* p = g_pre + ((size_t)b << 12) + hh;
    float xi = p[0], xf = p[1024], xo = p[2048], xg = p[3072];
    float ig = 1.f / (1.f + expf(-xi));
    float fg = 1.f / (1.f + expf(-xf));
    float og = 1.f / (1.f + expf(-xo));
    float gg = tanhf(xg);
    float c = fg * g_c[idx] + ig * gg;
    float h = og * tanhf(c);
    g_c[idx] = c;
    g_h16[idx] = __float2half(h);
    if (out) out[idx] = h;
}

// ---------------------------------------------------------------------------
extern "C" void kernel_launch(void* const* d_in, const int* in_sizes, int n_in,
                              void* d_out, int out_size) {
    const void*  caps  = d_in[0];
    const float* cnn   = (const float*)d_in[1];
    const float* sem   = (const float*)d_in[2];
    const float* embed = (const float*)d_in[3];
    const float* Wa    = (const float*)d_in[4];
    const float* Wb    = (const float*)d_in[5];
    const float* Wc    = (const float*)d_in[6];
    const float* Ua    = (const float*)d_in[7];
    const float* Ub    = (const float*)d_in[8];
    const float* Uc    = (const float*)d_in[9];
    const float* Ca    = (const float*)d_in[10];
    const float* Cb    = (const float*)d_in[11];
    const float* Cc    = (const float*)d_in[12];
    const float* bias  = (const float*)d_in[13];

    float *p_emb, *p_bufA, *p_bufB, *p_base, *p_SH, *p_pre;
    cudaGetSymbolAddress((void**)&p_emb,  g_emb);
    cudaGetSymbolAddress((void**)&p_bufA, g_bufA);
    cudaGetSymbolAddress((void**)&p_bufB, g_bufB);
    cudaGetSymbolAddress((void**)&p_base, g_base);
    cudaGetSymbolAddress((void**)&p_SH,   g_SH);
    cudaGetSymbolAddress((void**)&p_pre,  g_pre);

    __half *p_h16, *p_x16, *p_UaTh, *p_UaTl, *p_UcTh, *p_UcTl;
    cudaGetSymbolAddress((void**)&p_h16, g_h16);
    cudaGetSymbolAddress((void**)&p_x16, g_x16);
    cudaGetSymbolAddress((void**)&p_UaTh, g_UaT_h);
    cudaGetSymbolAddress((void**)&p_UaTl, g_UaT_l);
    cudaGetSymbolAddress((void**)&p_UcTh, g_UcT_h);
    cudaGetSymbolAddress((void**)&p_UcTl, g_UcT_l);

    cudaFuncSetAttribute(tcmma_kernel, cudaFuncAttributeMaxDynamicSharedMemorySize, MM_SMEM);

    dim3 gg(1024 / BN, BB / BM, 4);   // prologue fp32 GEMM grid
    dim3 tg(8, 4, 4);                 // tensor-core GEMM grid (128 CTAs)
    dim3 cg(32, 32, 4);               // weight conversion grid

    zero_hc_kernel<<<(BB * HH + 255) / 256, 256>>>();
    gather_emb_kernel<<<(BB * EE / 4 + 255) / 256, 256>>>(caps, embed);
    convT_kernel<<<cg, 256>>>(Ua, p_UaTh, p_UaTl);
    convT_kernel<<<cg, 256>>>(Uc, p_UcTh, p_UcTl);

    // base = (emb@Wa * sem@Wb)@Wc + (cnn@Ca * sem@Cb)@Cc + bias ; SH = sem@Ub
    gemm4_kernel<<<gg, 256>>>(p_emb,  EE,   0,    Wa, EE, nullptr, nullptr, p_bufA, 0);
    gemm4_kernel<<<gg, 256>>>(sem,    LL,   0,    Wb, LL, p_bufA,  nullptr, p_bufB, 1);
    gemm4_kernel<<<gg, 256>>>(p_bufB, 4096, 1024, Wc, II, nullptr, nullptr, p_base, 0);
    gemm4_kernel<<<gg, 256>>>(cnn,    FF,   0,    Ca, FF, nullptr, nullptr, p_bufA, 0);
    gemm4_kernel<<<gg, 256>>>(sem,    LL,   0,    Cb, LL, p_bufA,  nullptr, p_bufB, 1);
    gemm4_kernel<<<gg, 256>>>(p_bufB, 4096, 1024, Cc, II, p_base,  bias,    p_base, 2);
    gemm4_kernel<<<gg, 256>>>(sem,    LL,   0,    Ub, LL, nullptr, nullptr, p_SH,   0);

    for (int t = 0; t < TT; t++) {
        // X = (h @ UaT) * SH -> fp16
        tcmma_kernel<<<tg, 256, MM_SMEM>>>(p_h16, 1024, 0,
                                           p_UaTh, p_UaTl, p_SH,
                                           nullptr, p_x16, 1);
        // pre = (X @ UcT) + base -> fp32
        tcmma_kernel<<<tg, 256, MM_SMEM>>>(p_x16, 4096, 1024,
                                           p_UcTh, p_UcTl, p_base,
                                           p_pre, nullptr, 2);
        lstm_gate_kernel<<<(BB * HH + 255) / 256, 256>>>(t == TT - 1 ? (float*)d_out : nullptr);
    }
}

// round 7
// speedup vs baseline: 1.8202x; 1.3672x over previous
#include <cuda_runtime.h>
#include <cuda_fp16.h>
#include <cstdint>

// ---------------------------------------------------------------------------
// SemanticLSTM: B=256, T=80, E=512, I=H=1024, L=300, F=2048, V=32000
// Recurrence GEMMs on tensor cores via base-ISA mma.sync fp16, SINGLE pass:
// weights and activations both single fp16 (err ~2^-12 each, damped by the
// recurrence; measured headroom from R6 supports it). fp32 accumulate.
// ---------------------------------------------------------------------------

#define BB 256
#define TT 80
#define EE 512
#define II 1024
#define HH 1024
#define LL 300
#define FF 2048

// fp32 scratch
__device__ float g_emb [BB * EE];
__device__ float g_bufA[BB * 4 * II];
__device__ float g_bufB[BB * 4 * II];
__device__ float g_base[BB * 4 * HH];
__device__ float g_SH  [BB * 4 * II];
__device__ float g_pre [BB * 4 * HH];
__device__ float g_c   [BB * HH];

// fp16 activation buffers
__device__ __half g_h16[BB * HH];
__device__ __half g_x16[BB * 4 * II];
// transposed fp16 weights: UaT[g,i,h] = Ua[g,h,i]; UcT[g,h,i] = Uc[g,i,h]
__device__ __half g_UaT[4 * 1024 * 1024];
__device__ __half g_UcT[4 * 1024 * 1024];

// ---------------------------------------------------------------------------
// helpers (base-ISA: cp.async sm_80+, ldmatrix sm_75+, mma.sync sm_80+)
// ---------------------------------------------------------------------------
__device__ __forceinline__ uint32_t smem_u32(const void* p) {
    uint32_t a;
    asm("{ .reg .u64 t; cvta.to.shared.u64 t, %1; cvt.u32.u64 %0, t; }" : "=r"(a) : "l"(p));
    return a;
}
__device__ __forceinline__ void cpa16(uint32_t d, const void* s) {
    asm volatile("cp.async.cg.shared.global [%0], [%1], 16;" :: "r"(d), "l"(s));
}
__device__ __forceinline__ void cpa_commit() { asm volatile("cp.async.commit_group;"); }
template <int N>
__device__ __forceinline__ void cpa_wait() {
    asm volatile("cp.async.wait_group %0;" :: "n"(N) : "memory");
}
__device__ __forceinline__ void ldm_x4(uint32_t* r, uint32_t a) {
    asm volatile("ldmatrix.sync.aligned.m8n8.x4.shared.b16 {%0,%1,%2,%3}, [%4];"
                 : "=r"(r[0]), "=r"(r[1]), "=r"(r[2]), "=r"(r[3]) : "r"(a));
}
__device__ __forceinline__ void mma16816(float* d, const uint32_t* a, uint32_t b0, uint32_t b1) {
    asm volatile(
        "mma.sync.aligned.m16n8k16.row.col.f32.f16.f16.f32 "
        "{%0,%1,%2,%3},{%4,%5,%6,%7},{%8,%9},{%0,%1,%2,%3};"
        : "+f"(d[0]), "+f"(d[1]), "+f"(d[2]), "+f"(d[3])
        : "r"(a[0]), "r"(a[1]), "r"(a[2]), "r"(a[3]), "r"(b0), "r"(b1));
}

// ---------------------------------------------------------------------------
// zero state
// ---------------------------------------------------------------------------
__global__ __launch_bounds__(256) void zero_hc_kernel() {
    int idx = blockIdx.x * 256 + threadIdx.x;
    if (idx < BB * HH) {
        g_c[idx] = 0.f;
        g_h16[idx] = __float2half(0.f);
    }
}

// ---------------------------------------------------------------------------
// gather emb = embed[captions[:,0]]  (int64/int32 robust)
// ---------------------------------------------------------------------------
__global__ __launch_bounds__(256) void gather_emb_kernel(const void* __restrict__ caps,
                                                         const float* __restrict__ embed) {
    __shared__ int is64;
    if (threadIdx.x == 0) {
        const int* p = (const int*)caps;
        int z = 1;
        for (int k = 0; k < 16; k++)
            if (p[2 * k + 1] != 0) z = 0;
        is64 = z;
    }
    __syncthreads();
    int idx = blockIdx.x * 256 + threadIdx.x;
    if (idx >= BB * (EE / 4)) return;
    int b  = idx / (EE / 4);
    int e4 = idx % (EE / 4);
    long long cap;
    if (is64) cap = ((const long long*)caps)[(long long)b * TT];
    else      cap = (long long)((const int*)caps)[b * TT];
    float4 v = ((const float4*)embed)[cap * (EE / 4) + e4];
    ((float4*)g_emb)[idx] = v;
}

// ---------------------------------------------------------------------------
// transpose + fp16 convert: dst[g,a,b] = fp16(src[g,b,a]); grid (32,32,4)
// ---------------------------------------------------------------------------
__global__ __launch_bounds__(256) void convT_kernel(const float* __restrict__ src,
                                                    __half* __restrict__ dh) {
    __shared__ float t[32][33];
    int g  = blockIdx.z;
    int x0 = blockIdx.x * 32;
    int y0 = blockIdx.y * 32;
    int tx = threadIdx.x & 31, ty = threadIdx.x >> 5;
    const float* s = src + (size_t)g * 1048576;
#pragma unroll
    for (int k = 0; k < 4; k++)
        t[ty + k * 8][tx] = s[(size_t)(y0 + ty + k * 8) * 1024 + x0 + tx];
    __syncthreads();
    __half* oh = dh + (size_t)g * 1048576;
#pragma unroll
    for (int k = 0; k < 4; k++) {
        float v = t[tx][ty + k * 8];
        size_t o = (size_t)(x0 + ty + k * 8) * 1024 + y0 + tx;
        oh[o] = __float2half(v);
    }
}

// ---------------------------------------------------------------------------
// fp32 prologue SGEMM (7 launches only)
// ---------------------------------------------------------------------------
#define BM 64
#define BN 128
#define BK 16

__global__ __launch_bounds__(256) void gemm4_kernel(
    const float* __restrict__ A, int lda, int agoff,
    const float* __restrict__ W, int K,
    const float* Z, const float* __restrict__ bias,
    float* C, int mode)
{
    const int N = 1024;
    const int g  = blockIdx.z;
    const int bx = blockIdx.x;
    const int by = blockIdx.y;

    __shared__ float As[BK][BM];
    __shared__ float Bs[BK][BN];

    const int tid = threadIdx.x;
    const int tx  = tid & 15;
    const int ty  = tid >> 4;

    const float* Ag = A + (size_t)g * agoff;
    const float* Wg = W + (size_t)g * K * N + bx * BN;

    float acc[4][8];
#pragma unroll
    for (int i = 0; i < 4; i++)
#pragma unroll
        for (int j = 0; j < 8; j++) acc[i][j] = 0.f;

    const int arow = tid >> 2;
    const int ac   = (tid & 3) * 4;

    for (int kk = 0; kk < K; kk += BK) {
        {
            const int m = by * BM + arow;
            const float* ap = Ag + (size_t)m * lda + kk + ac;
#pragma unroll
            for (int j = 0; j < 4; j++) {
                float v = (kk + ac + j < K) ? ap[j] : 0.f;
                As[ac + j][arow] = v;
            }
        }
#pragma unroll
        for (int r = 0; r < 2; r++) {
            int idx  = tid + r * 256;
            int brow = idx >> 5;
            int bc   = (idx & 31) * 4;
            int kg   = kk + brow;
            float4 v;
            if (kg < K) v = *(const float4*)(Wg + (size_t)kg * N + bc);
            else        v = make_float4(0.f, 0.f, 0.f, 0.f);
            *(float4*)&Bs[brow][bc] = v;
        }
        __syncthreads();

#pragma unroll
        for (int k = 0; k < BK; k++) {
            float4 av = *(const float4*)&As[k][ty * 4];
            float4 b0 = *(const float4*)&Bs[k][tx * 8];
            float4 b1 = *(const float4*)&Bs[k][tx * 8 + 4];
            float a[4] = {av.x, av.y, av.z, av.w};
            float b[8] = {b0.x, b0.y, b0.z, b0.w, b1.x, b1.y, b1.z, b1.w};
#pragma unroll
            for (int i = 0; i < 4; i++)
#pragma unroll
                for (int j = 0; j < 8; j++)
                    acc[i][j] = fmaf(a[i], b[j], acc[i][j]);
        }
        __syncthreads();
    }

#pragma unroll
    for (int i = 0; i < 4; i++) {
        const int m = by * BM + ty * 4 + i;
        const int n0 = bx * BN + tx * 8;
        size_t row = (size_t)m * 4096 + (size_t)g * 1024 + n0;
#pragma unroll
        for (int j = 0; j < 8; j++) {
            float v = acc[i][j];
            if (mode == 1)      v *= Z[row + j];
            else if (mode == 2) {
                v += Z[row + j];
                if (bias) v += bias[g * 1024 + n0 + j];
            }
            C[row + j] = v;
        }
    }
}

// ---------------------------------------------------------------------------
// Tensor-core fp16 single-pass GEMM via mma.sync.m16n8k16.
// CTA tile M=64 x N=128, BK=64, K=1024 (16 chunks), double-buffered cp.async.
// grid (8 n-tiles, 4 m-tiles, 4 gates) = 128 CTAs, 256 threads (8 warps 32x32).
// mode 1: out = acc * Z -> fp16 ; mode 2: out = acc + Z -> fp32
// ---------------------------------------------------------------------------
#define ASTRIDE  144                     // bytes per smem row (64 fp16 + pad)
#define A_TILE_B (64  * ASTRIDE)         // 9216
#define B_TILE_B (128 * ASTRIDE)         // 18432
#define STAGE_B  (A_TILE_B + B_TILE_B)   // 27648: A | B
#define MM_SMEM  (2 * STAGE_B)           // 55296

__device__ __forceinline__ void load_stage(
    uint32_t sa, uint32_t sb,
    const __half* __restrict__ A, int lda,
    const __half* __restrict__ B,
    int k0, int tid)
{
    // A: 64 rows x 8 chunks of 16B = 512 cp.async
#pragma unroll
    for (int r = 0; r < 2; r++) {
        int id  = tid + (r << 8);
        int row = id >> 3;
        int cb  = id & 7;
        uint32_t d = sa + row * ASTRIDE + cb * 16;
        size_t  sp = (size_t)row * lda + k0 + cb * 8;
        cpa16(d, A + sp);
    }
    // B: 128 rows x 8 chunks of 16B = 1024 cp.async
#pragma unroll
    for (int r = 0; r < 4; r++) {
        int id  = tid + (r << 8);
        int row = id >> 3;
        int cb  = id & 7;
        uint32_t d = sb + row * ASTRIDE + cb * 16;
        size_t  sp = (size_t)row * 1024 + k0 + cb * 8;
        cpa16(d, B + sp);
    }
}

__global__ __launch_bounds__(256, 1) void tcmma_kernel(
    const __half* __restrict__ A, int lda, int agoff,
    const __half* __restrict__ B,
    const float* __restrict__ Z,
    float* outF, __half* outH, int mode)
{
    extern __shared__ char dsm[];
    const uint32_t sbase = smem_u32(dsm);

    const int g    = blockIdx.z;
    const int nx   = blockIdx.x;   // 0..7 (128-wide n tile within gate)
    const int my   = blockIdx.y;   // 0..3 (64-wide m tile)
    const int tid  = threadIdx.x;
    const int lane = tid & 31;
    const int warp = tid >> 5;
    const int wm   = warp & 1;     // 0..1 -> 32 rows
    const int wn   = warp >> 1;    // 0..3 -> 32 cols

    const __half* Ap = A + (size_t)g * agoff + (size_t)(my * 64) * lda;
    const __half* Bp = B + ((size_t)g * 1024 + nx * 128) * 1024;

    float acc[2][4][4];
#pragma unroll
    for (int i = 0; i < 2; i++)
#pragma unroll
        for (int j = 0; j < 4; j++)
#pragma unroll
            for (int k = 0; k < 4; k++) acc[i][j][k] = 0.f;

    // per-lane ldmatrix base offsets
    const int rin  = lane & 7;
    const int quad = lane >> 3;
    const uint32_t aoff = ((quad & 1) * 8 + rin) * ASTRIDE + (quad >> 1) * 16;
    const uint32_t boff = ((quad >> 1) * 8 + rin) * ASTRIDE + (quad & 1) * 16;
    const uint32_t aBase = sbase + wm * 32 * ASTRIDE + aoff;
    const uint32_t bBase = sbase + A_TILE_B + wn * 32 * ASTRIDE + boff;

    // preload chunk 0
    load_stage(sbase, sbase + A_TILE_B, Ap, lda, Bp, 0, tid);
    cpa_commit();

    const int NC = 16;
    for (int c = 0; c < NC; c++) {
        const uint32_t soff = (c & 1) * STAGE_B;
        if (c + 1 < NC) {
            const uint32_t s2 = ((c + 1) & 1) * STAGE_B;
            load_stage(sbase + s2, sbase + s2 + A_TILE_B, Ap, lda, Bp, (c + 1) * 64, tid);
            cpa_commit();
            cpa_wait<1>();
        } else {
            cpa_wait<0>();
        }
        __syncthreads();

        const uint32_t aCur = aBase + soff;
        const uint32_t bCur = bBase + soff;
#pragma unroll
        for (int ks = 0; ks < 4; ks++) {
            uint32_t a[2][4], b[2][4];
            const uint32_t ka = aCur + ks * 32;
            const uint32_t kb = bCur + ks * 32;
            ldm_x4(a[0], ka);
            ldm_x4(a[1], ka + 16 * ASTRIDE);
            ldm_x4(b[0], kb);
            ldm_x4(b[1], kb + 16 * ASTRIDE);
#pragma unroll
            for (int im = 0; im < 2; im++)
#pragma unroll
                for (int jn = 0; jn < 4; jn++) {
                    const int jp = jn >> 1, q = (jn & 1) * 2;
                    mma16816(acc[im][jn], a[im], b[jp][q], b[jp][q + 1]);
                }
        }
        __syncthreads();
    }

    // epilogue
#pragma unroll
    for (int im = 0; im < 2; im++) {
        const int m0 = my * 64 + wm * 32 + im * 16 + (lane >> 2);
#pragma unroll
        for (int jn = 0; jn < 4; jn++) {
            const int n0 = nx * 128 + wn * 32 + jn * 8 + (lane & 3) * 2;
            const size_t p0 = (size_t)m0 * 4096 + (size_t)g * 1024 + n0;
            const size_t p1 = p0 + 8 * 4096;   // m0 + 8
            const float* a = acc[im][jn];
            if (mode == 1) {
                __half2 h01 = __floats2half2_rn(a[0] * Z[p0], a[1] * Z[p0 + 1]);
                __half2 h23 = __floats2half2_rn(a[2] * Z[p1], a[3] * Z[p1 + 1]);
                *(__half2*)&outH[p0] = h01;
                *(__half2*)&outH[p1] = h23;
            } else {
                outF[p0]     = a[0] + Z[p0];
                outF[p0 + 1] = a[1] + Z[p0 + 1];
                outF[p1]     = a[2] + Z[p1];
                outF[p1 + 1] = a[3] + Z[p1 + 1];
            }
        }
    }
}

// ---------------------------------------------------------------------------
// LSTM gate update: reads g_pre, updates g_c, writes h as fp16
// ---------------------------------------------------------------------------
__global__ __launch_bounds__(256) void lstm_gate_kernel(float* out) {
    int idx = blockIdx.x * 256 + threadIdx.x;
    if (idx >= BB * HH) return;
    int b  = idx >> 10;
    int hh = idx & 1023;
    const float* p = g_pre + ((size_t)b << 12) + hh;
    float xi = p[0], xf = p[1024], xo = p[2048], xg = p[3072];
    float ig = 1.f / (1.f + expf(-xi));
    float fg = 1.f / (1.f + expf(-xf));
    float og = 1.f / (1.f + expf(-xo));
    float gg = tanhf(xg);
    float c = fg * g_c[idx] + ig * gg;
    float h = og * tanhf(c);
    g_c[idx] = c;
    g_h16[idx] = __float2half(h);
    if (out) out[idx] = h;
}

// ---------------------------------------------------------------------------
extern "C" void kernel_launch(void* const* d_in, const int* in_sizes, int n_in,
                              void* d_out, int out_size) {
    const void*  caps  = d_in[0];
    const float* cnn   = (const float*)d_in[1];
    const float* sem   = (const float*)d_in[2];
    const float* embed = (const float*)d_in[3];
    const float* Wa    = (const float*)d_in[4];
    const float* Wb    = (const float*)d_in[5];
    const float* Wc    = (const float*)d_in[6];
    const float* Ua    = (const float*)d_in[7];
    const float* Ub    = (const float*)d_in[8];
    const float* Uc    = (const float*)d_in[9];
    const float* Ca    = (const float*)d_in[10];
    const float* Cb    = (const float*)d_in[11];
    const float* Cc    = (const float*)d_in[12];
    const float* bias  = (const float*)d_in[13];

    float *p_emb, *p_bufA, *p_bufB, *p_base, *p_SH, *p_pre;
    cudaGetSymbolAddress((void**)&p_emb,  g_emb);
    cudaGetSymbolAddress((void**)&p_bufA, g_bufA);
    cudaGetSymbolAddress((void**)&p_bufB, g_bufB);
    cudaGetSymbolAddress((void**)&p_base, g_base);
    cudaGetSymbolAddress((void**)&p_SH,   g_SH);
    cudaGetSymbolAddress((void**)&p_pre,  g_pre);

    __half *p_h16, *p_x16, *p_UaT, *p_UcT;
    cudaGetSymbolAddress((void**)&p_h16, g_h16);
    cudaGetSymbolAddress((void**)&p_x16, g_x16);
    cudaGetSymbolAddress((void**)&p_UaT, g_UaT);
    cudaGetSymbolAddress((void**)&p_UcT, g_UcT);

    cudaFuncSetAttribute(tcmma_kernel, cudaFuncAttributeMaxDynamicSharedMemorySize, MM_SMEM);

    dim3 gg(1024 / BN, BB / BM, 4);   // prologue fp32 GEMM grid
    dim3 tg(8, 4, 4);                 // tensor-core GEMM grid (128 CTAs)
    dim3 cg(32, 32, 4);               // weight conversion grid

    zero_hc_kernel<<<(BB * HH + 255) / 256, 256>>>();
    gather_emb_kernel<<<(BB * EE / 4 + 255) / 256, 256>>>(caps, embed);
    convT_kernel<<<cg, 256>>>(Ua, p_UaT);
    convT_kernel<<<cg, 256>>>(Uc, p_UcT);

    // base = (emb@Wa * sem@Wb)@Wc + (cnn@Ca * sem@Cb)@Cc + bias ; SH = sem@Ub
    gemm4_kernel<<<gg, 256>>>(p_emb,  EE,   0,    Wa, EE, nullptr, nullptr, p_bufA, 0);
    gemm4_kernel<<<gg, 256>>>(sem,    LL,   0,    Wb, LL, p_bufA,  nullptr, p_bufB, 1);
    gemm4_kernel<<<gg, 256>>>(p_bufB, 4096, 1024, Wc, II, nullptr, nullptr, p_base, 0);
    gemm4_kernel<<<gg, 256>>>(cnn,    FF,   0,    Ca, FF, nullptr, nullptr, p_bufA, 0);
    gemm4_kernel<<<gg, 256>>>(sem,    LL,   0,    Cb, LL, p_bufA,  nullptr, p_bufB, 1);
    gemm4_kernel<<<gg, 256>>>(p_bufB, 4096, 1024, Cc, II, p_base,  bias,    p_base, 2);
    gemm4_kernel<<<gg, 256>>>(sem,    LL,   0,    Ub, LL, nullptr, nullptr, p_SH,   0);

    for (int t = 0; t < TT; t++) {
        // X = (h @ UaT) * SH -> fp16
        tcmma_kernel<<<tg, 256, MM_SMEM>>>(p_h16, 1024, 0,
                                           p_UaT, p_SH, nullptr, p_x16, 1);
        // pre = (X @ UcT) + base -> fp32
        tcmma_kernel<<<tg, 256, MM_SMEM>>>(p_x16, 4096, 1024,
                                           p_UcT, p_base, p_pre, nullptr, 2);
        lstm_gate_kernel<<<(BB * HH + 255) / 256, 256>>>(t == TT - 1 ? (float*)d_out : nullptr);
    }
}

// round 8
// speedup vs baseline: 1.9686x; 1.0815x over previous
#include <cuda_runtime.h>
#include <cuda_fp16.h>
#include <cstdint>

// ---------------------------------------------------------------------------
// SemanticLSTM: B=256, T=80, E=512, I=H=1024, L=300, F=2048, V=32000
// Recurrence GEMMs: fp16 mma.sync, split-K=2 with 128x128 CTA tiles to fix the
// cp.async-issue bound (682 MAC/load-op vs 341 before). Deterministic partial
// buffers; E1 fuses (p0+p1)*SH -> fp16; gate fuses p0+p1+base.
// ---------------------------------------------------------------------------

#define BB 256
#define TT 80
#define EE 512
#define II 1024
#define HH 1024
#define LL 300
#define FF 2048

// fp32 scratch
__device__ float g_emb [BB * EE];
__device__ float g_bufA[BB * 4 * II];
__device__ float g_bufB[BB * 4 * II];
__device__ float g_base[BB * 4 * HH];
__device__ float g_SH  [BB * 4 * II];
__device__ float g_c   [BB * HH];
// split-K partial buffers (shared by GEMM1/GEMM2, consumed before reuse)
__device__ float g_p0  [BB * 4 * HH];
__device__ float g_p1  [BB * 4 * HH];

// fp16 activation buffers
__device__ __half g_h16[BB * HH];
__device__ __half g_x16[BB * 4 * II];
// transposed fp16 weights: UaT[g,i,h] = Ua[g,h,i]; UcT[g,h,i] = Uc[g,i,h]
__device__ __half g_UaT[4 * 1024 * 1024];
__device__ __half g_UcT[4 * 1024 * 1024];

// ---------------------------------------------------------------------------
// helpers (base-ISA: cp.async sm_80+, ldmatrix sm_75+, mma.sync sm_80+)
// ---------------------------------------------------------------------------
__device__ __forceinline__ uint32_t smem_u32(const void* p) {
    uint32_t a;
    asm("{ .reg .u64 t; cvta.to.shared.u64 t, %1; cvt.u32.u64 %0, t; }" : "=r"(a) : "l"(p));
    return a;
}
__device__ __forceinline__ void cpa16(uint32_t d, const void* s) {
    asm volatile("cp.async.cg.shared.global [%0], [%1], 16;" :: "r"(d), "l"(s));
}
__device__ __forceinline__ void cpa_commit() { asm volatile("cp.async.commit_group;"); }
template <int N>
__device__ __forceinline__ void cpa_wait() {
    asm volatile("cp.async.wait_group %0;" :: "n"(N) : "memory");
}
__device__ __forceinline__ void ldm_x4(uint32_t* r, uint32_t a) {
    asm volatile("ldmatrix.sync.aligned.m8n8.x4.shared.b16 {%0,%1,%2,%3}, [%4];"
                 : "=r"(r[0]), "=r"(r[1]), "=r"(r[2]), "=r"(r[3]) : "r"(a));
}
__device__ __forceinline__ void mma16816(float* d, const uint32_t* a, uint32_t b0, uint32_t b1) {
    asm volatile(
        "mma.sync.aligned.m16n8k16.row.col.f32.f16.f16.f32 "
        "{%0,%1,%2,%3},{%4,%5,%6,%7},{%8,%9},{%0,%1,%2,%3};"
        : "+f"(d[0]), "+f"(d[1]), "+f"(d[2]), "+f"(d[3])
        : "r"(a[0]), "r"(a[1]), "r"(a[2]), "r"(a[3]), "r"(b0), "r"(b1));
}

// ---------------------------------------------------------------------------
// zero state
// ---------------------------------------------------------------------------
__global__ __launch_bounds__(256) void zero_hc_kernel() {
    int idx = blockIdx.x * 256 + threadIdx.x;
    if (idx < BB * HH) {
        g_c[idx] = 0.f;
        g_h16[idx] = __float2half(0.f);
    }
}

// ---------------------------------------------------------------------------
// gather emb = embed[captions[:,0]]  (int64/int32 robust)
// ---------------------------------------------------------------------------
__global__ __launch_bounds__(256) void gather_emb_kernel(const void* __restrict__ caps,
                                                         const float* __restrict__ embed) {
    __shared__ int is64;
    if (threadIdx.x == 0) {
        const int* p = (const int*)caps;
        int z = 1;
        for (int k = 0; k < 16; k++)
            if (p[2 * k + 1] != 0) z = 0;
        is64 = z;
    }
    __syncthreads();
    int idx = blockIdx.x * 256 + threadIdx.x;
    if (idx >= BB * (EE / 4)) return;
    int b  = idx / (EE / 4);
    int e4 = idx % (EE / 4);
    long long cap;
    if (is64) cap = ((const long long*)caps)[(long long)b * TT];
    else      cap = (long long)((const int*)caps)[b * TT];
    float4 v = ((const float4*)embed)[cap * (EE / 4) + e4];
    ((float4*)g_emb)[idx] = v;
}

// ---------------------------------------------------------------------------
// transpose + fp16 convert: dst[g,a,b] = fp16(src[g,b,a]); grid (32,32,4)
// ---------------------------------------------------------------------------
__global__ __launch_bounds__(256) void convT_kernel(const float* __restrict__ src,
                                                    __half* __restrict__ dh) {
    __shared__ float t[32][33];
    int g  = blockIdx.z;
    int x0 = blockIdx.x * 32;
    int y0 = blockIdx.y * 32;
    int tx = threadIdx.x & 31, ty = threadIdx.x >> 5;
    const float* s = src + (size_t)g * 1048576;
#pragma unroll
    for (int k = 0; k < 4; k++)
        t[ty + k * 8][tx] = s[(size_t)(y0 + ty + k * 8) * 1024 + x0 + tx];
    __syncthreads();
    __half* oh = dh + (size_t)g * 1048576;
#pragma unroll
    for (int k = 0; k < 4; k++) {
        float v = t[tx][ty + k * 8];
        size_t o = (size_t)(x0 + ty + k * 8) * 1024 + y0 + tx;
        oh[o] = __float2half(v);
    }
}

// ---------------------------------------------------------------------------
// fp32 prologue SGEMM (7 launches only)
// ---------------------------------------------------------------------------
#define BM 64
#define BN 128
#define BK 16

__global__ __launch_bounds__(256) void gemm4_kernel(
    const float* __restrict__ A, int lda, int agoff,
    const float* __restrict__ W, int K,
    const float* Z, const float* __restrict__ bias,
    float* C, int mode)
{
    const int N = 1024;
    const int g  = blockIdx.z;
    const int bx = blockIdx.x;
    const int by = blockIdx.y;

    __shared__ float As[BK][BM];
    __shared__ float Bs[BK][BN];

    const int tid = threadIdx.x;
    const int tx  = tid & 15;
    const int ty  = tid >> 4;

    const float* Ag = A + (size_t)g * agoff;
    const float* Wg = W + (size_t)g * K * N + bx * BN;

    float acc[4][8];
#pragma unroll
    for (int i = 0; i < 4; i++)
#pragma unroll
        for (int j = 0; j < 8; j++) acc[i][j] = 0.f;

    const int arow = tid >> 2;
    const int ac   = (tid & 3) * 4;

    for (int kk = 0; kk < K; kk += BK) {
        {
            const int m = by * BM + arow;
            const float* ap = Ag + (size_t)m * lda + kk + ac;
#pragma unroll
            for (int j = 0; j < 4; j++) {
                float v = (kk + ac + j < K) ? ap[j] : 0.f;
                As[ac + j][arow] = v;
            }
        }
#pragma unroll
        for (int r = 0; r < 2; r++) {
            int idx  = tid + r * 256;
            int brow = idx >> 5;
            int bc   = (idx & 31) * 4;
            int kg   = kk + brow;
            float4 v;
            if (kg < K) v = *(const float4*)(Wg + (size_t)kg * N + bc);
            else        v = make_float4(0.f, 0.f, 0.f, 0.f);
            *(float4*)&Bs[brow][bc] = v;
        }
        __syncthreads();

#pragma unroll
        for (int k = 0; k < BK; k++) {
            float4 av = *(const float4*)&As[k][ty * 4];
            float4 b0 = *(const float4*)&Bs[k][tx * 8];
            float4 b1 = *(const float4*)&Bs[k][tx * 8 + 4];
            float a[4] = {av.x, av.y, av.z, av.w};
            float b[8] = {b0.x, b0.y, b0.z, b0.w, b1.x, b1.y, b1.z, b1.w};
#pragma unroll
            for (int i = 0; i < 4; i++)
#pragma unroll
                for (int j = 0; j < 8; j++)
                    acc[i][j] = fmaf(a[i], b[j], acc[i][j]);
        }
        __syncthreads();
    }

#pragma unroll
    for (int i = 0; i < 4; i++) {
        const int m = by * BM + ty * 4 + i;
        const int n0 = bx * BN + tx * 8;
        size_t row = (size_t)m * 4096 + (size_t)g * 1024 + n0;
#pragma unroll
        for (int j = 0; j < 8; j++) {
            float v = acc[i][j];
            if (mode == 1)      v *= Z[row + j];
            else if (mode == 2) {
                v += Z[row + j];
                if (bias) v += bias[g * 1024 + n0 + j];
            }
            C[row + j] = v;
        }
    }
}

// ---------------------------------------------------------------------------
// Split-K tensor-core fp16 GEMM via mma.sync.m16n8k16.
// CTA tile M=128 x N=128, K-half=512 (8 chunks of 64), double-buffered.
// grid (8 nx, 4 myk{my,k}, 4 g) = 128 CTAs, 256 threads.
// 8 warps: wm = warp&3 (32 rows), wn = warp>>2 (64 cols). Warp tile 32x64.
// Writes raw f32 partial tile to part (p0 or p1 by k-half).
// ---------------------------------------------------------------------------
#define ASTRIDE  144                     // bytes per smem row (64 fp16 + pad)
#define A_TILE_B (128 * ASTRIDE)         // 18432
#define B_TILE_B (128 * ASTRIDE)         // 18432
#define STAGE_B  (A_TILE_B + B_TILE_B)   // 36864
#define MM_SMEM  (2 * STAGE_B)           // 73728

__device__ __forceinline__ void load_stage(
    uint32_t sa, uint32_t sb,
    const __half* __restrict__ A, int lda,
    const __half* __restrict__ B,
    int k0, int tid)
{
    // A: 128 rows x 8 chunks of 16B = 1024 cp.async
#pragma unroll
    for (int r = 0; r < 4; r++) {
        int id  = tid + (r << 8);
        int row = id >> 3;
        int cb  = id & 7;
        uint32_t d = sa + row * ASTRIDE + cb * 16;
        size_t  sp = (size_t)row * lda + k0 + cb * 8;
        cpa16(d, A + sp);
    }
    // B: 128 rows x 8 chunks of 16B = 1024 cp.async
#pragma unroll
    for (int r = 0; r < 4; r++) {
        int id  = tid + (r << 8);
        int row = id >> 3;
        int cb  = id & 7;
        uint32_t d = sb + row * ASTRIDE + cb * 16;
        size_t  sp = (size_t)row * 1024 + k0 + cb * 8;
        cpa16(d, B + sp);
    }
}

__global__ __launch_bounds__(256, 1) void tcsplit_kernel(
    const __half* __restrict__ A, int lda, int agoff,
    const __half* __restrict__ B,
    float* __restrict__ part0, float* __restrict__ part1)
{
    extern __shared__ char dsm[];
    const uint32_t sbase = smem_u32(dsm);

    const int g    = blockIdx.z;
    const int nx   = blockIdx.x;        // 0..7 : 128-wide n tile within gate
    const int my   = blockIdx.y >> 1;   // 0..1 : 128-row m tile
    const int kh   = blockIdx.y & 1;    // 0..1 : K half
    const int tid  = threadIdx.x;
    const int lane = tid & 31;
    const int warp = tid >> 5;
    const int wm   = warp & 3;          // 4 x 32 rows
    const int wn   = warp >> 2;         // 2 x 64 cols

    const __half* Ap = A + (size_t)g * agoff + (size_t)(my * 128) * lda + kh * 512;
    const __half* Bp = B + ((size_t)g * 1024 + nx * 128) * 1024 + kh * 512;
    float* outP = kh ? part1 : part0;

    float acc[2][8][4];
#pragma unroll
    for (int i = 0; i < 2; i++)
#pragma unroll
        for (int j = 0; j < 8; j++)
#pragma unroll
            for (int k = 0; k < 4; k++) acc[i][j][k] = 0.f;

    // per-lane ldmatrix base offsets
    const int rin  = lane & 7;
    const int quad = lane >> 3;
    // A x4: regs = (m0-7,klo),(m8-15,klo),(m0-7,khi),(m8-15,khi)
    const uint32_t aoff = ((quad & 1) * 8 + rin) * ASTRIDE + (quad >> 1) * 16;
    // B x4: regs = (n0-7,klo),(n0-7,khi),(n8-15,klo),(n8-15,khi)
    const uint32_t boff = ((quad >> 1) * 8 + rin) * ASTRIDE + (quad & 1) * 16;
    const uint32_t aBase = sbase + wm * 32 * ASTRIDE + aoff;
    const uint32_t bBase = sbase + A_TILE_B + wn * 64 * ASTRIDE + boff;

    // preload chunk 0
    load_stage(sbase, sbase + A_TILE_B, Ap, lda, Bp, 0, tid);
    cpa_commit();

    const int NC = 8;
    for (int c = 0; c < NC; c++) {
        const uint32_t soff = (c & 1) * STAGE_B;
        if (c + 1 < NC) {
            const uint32_t s2 = ((c + 1) & 1) * STAGE_B;
            load_stage(sbase + s2, sbase + s2 + A_TILE_B, Ap, lda, Bp, (c + 1) * 64, tid);
            cpa_commit();
            cpa_wait<1>();
        } else {
            cpa_wait<0>();
        }
        __syncthreads();

        const uint32_t aCur = aBase + soff;
        const uint32_t bCur = bBase + soff;
#pragma unroll
        for (int ks = 0; ks < 4; ks++) {
            uint32_t a[2][4], b[4][4];
            const uint32_t ka = aCur + ks * 32;
            const uint32_t kb = bCur + ks * 32;
            ldm_x4(a[0], ka);
            ldm_x4(a[1], ka + 16 * ASTRIDE);
            ldm_x4(b[0], kb);
            ldm_x4(b[1], kb + 16 * ASTRIDE);
            ldm_x4(b[2], kb + 32 * ASTRIDE);
            ldm_x4(b[3], kb + 48 * ASTRIDE);
#pragma unroll
            for (int im = 0; im < 2; im++)
#pragma unroll
                for (int jn = 0; jn < 8; jn++) {
                    const int jp = jn >> 1, q = (jn & 1) * 2;
                    mma16816(acc[im][jn], a[im], b[jp][q], b[jp][q + 1]);
                }
        }
        __syncthreads();
    }

    // epilogue: raw f32 partial stores
#pragma unroll
    for (int im = 0; im < 2; im++) {
        const int m0 = my * 128 + wm * 32 + im * 16 + (lane >> 2);
#pragma unroll
        for (int jn = 0; jn < 8; jn++) {
            const int n0 = nx * 128 + wn * 64 + jn * 8 + (lane & 3) * 2;
            const size_t p0 = (size_t)m0 * 4096 + (size_t)g * 1024 + n0;
            const size_t p1 = p0 + 8 * 4096;   // m0 + 8
            const float* a = acc[im][jn];
            *(float2*)&outP[p0] = make_float2(a[0], a[1]);
            *(float2*)&outP[p1] = make_float2(a[2], a[3]);
        }
    }
}

// ---------------------------------------------------------------------------
// E1: x16 = fp16((p0 + p1) * SH)   over B*4*I = 1M elements, 4 per thread
// ---------------------------------------------------------------------------
__global__ __launch_bounds__(256) void e1_kernel() {
    int idx = (blockIdx.x * 256 + threadIdx.x) * 4;
    float4 a = *(const float4*)&g_p0[idx];
    float4 b = *(const float4*)&g_p1[idx];
    float4 s = *(const float4*)&g_SH[idx];
    float x0 = (a.x + b.x) * s.x;
    float x1 = (a.y + b.y) * s.y;
    float x2 = (a.z + b.z) * s.z;
    float x3 = (a.w + b.w) * s.w;
    __half2 h01 = __floats2half2_rn(x0, x1);
    __half2 h23 = __floats2half2_rn(x2, x3);
    *(__half2*)&g_x16[idx]     = h01;
    *(__half2*)&g_x16[idx + 2] = h23;
}

// ---------------------------------------------------------------------------
// LSTM gate update: pre = p0 + p1 + base; updates g_c, writes h fp16
// ---------------------------------------------------------------------------
__global__ __launch_bounds__(256) void lstm_gate_kernel(float* out) {
    int idx = blockIdx.x * 256 + threadIdx.x;
    if (idx >= BB * HH) return;
    int b  = idx >> 10;
    int hh = idx & 1023;
    size_t off = ((size_t)b << 12) + hh;
    float xi = g_p0[off]        + g_p1[off]        + g_base[off];
    float xf = g_p0[off + 1024] + g_p1[off + 1024] + g_base[off + 1024];
    float xo = g_p0[off + 2048] + g_p1[off + 2048] + g_base[off + 2048];
    float xg = g_p0[off + 3072] + g_p1[off + 3072] + g_base[off + 3072];
    float ig = 1.f / (1.f + expf(-xi));
    float fg = 1.f / (1.f + expf(-xf));
    float og = 1.f / (1.f + expf(-xo));
    float gg = tanhf(xg);
    float c = fg * g_c[idx] + ig * gg;
    float h = og * tanhf(c);
    g_c[idx] = c;
    g_h16[idx] = __float2half(h);
    if (out) out[idx] = h;
}

// ---------------------------------------------------------------------------
extern "C" void kernel_launch(void* const* d_in, const int* in_sizes, int n_in,
                              void* d_out, int out_size) {
    const void*  caps  = d_in[0];
    const float* cnn   = (const float*)d_in[1];
    const float* sem   = (const float*)d_in[2];
    const float* embed = (const float*)d_in[3];
    const float* Wa    = (const float*)d_in[4];
    const float* Wb    = (const float*)d_in[5];
    const float* Wc    = (const float*)d_in[6];
    const float* Ua    = (const float*)d_in[7];
    const float* Ub    = (const float*)d_in[8];
    const float* Uc    = (const float*)d_in[9];
    const float* Ca    = (const float*)d_in[10];
    const float* Cb    = (const float*)d_in[11];
    const float* Cc    = (const float*)d_in[12];
    const float* bias  = (const float*)d_in[13];

    float *p_emb, *p_bufA, *p_bufB, *p_base, *p_SH;
    cudaGetSymbolAddress((void**)&p_emb,  g_emb);
    cudaGetSymbolAddress((void**)&p_bufA, g_bufA);
    cudaGetSymbolAddress((void**)&p_bufB, g_bufB);
    cudaGetSymbolAddress((void**)&p_base, g_base);
    cudaGetSymbolAddress((void**)&p_SH,   g_SH);

    float *p_p0, *p_p1;
    cudaGetSymbolAddress((void**)&p_p0, g_p0);
    cudaGetSymbolAddress((void**)&p_p1, g_p1);

    __half *p_h16, *p_x16, *p_UaT, *p_UcT;
    cudaGetSymbolAddress((void**)&p_h16, g_h16);
    cudaGetSymbolAddress((void**)&p_x16, g_x16);
    cudaGetSymbolAddress((void**)&p_UaT, g_UaT);
    cudaGetSymbolAddress((void**)&p_UcT, g_UcT);

    cudaFuncSetAttribute(tcsplit_kernel, cudaFuncAttributeMaxDynamicSharedMemorySize, MM_SMEM);

    dim3 gg(1024 / BN, BB / BM, 4);   // prologue fp32 GEMM grid
    dim3 tg(8, 4, 4);                 // split-K TC GEMM grid (128 CTAs)
    dim3 cg(32, 32, 4);               // weight conversion grid

    zero_hc_kernel<<<(BB * HH + 255) / 256, 256>>>();
    gather_emb_kernel<<<(BB * EE / 4 + 255) / 256, 256>>>(caps, embed);
    convT_kernel<<<cg, 256>>>(Ua, p_UaT);
    convT_kernel<<<cg, 256>>>(Uc, p_UcT);

    // base = (emb@Wa * sem@Wb)@Wc + (cnn@Ca * sem@Cb)@Cc + bias ; SH = sem@Ub
    gemm4_kernel<<<gg, 256>>>(p_emb,  EE,   0,    Wa, EE, nullptr, nullptr, p_bufA, 0);
    gemm4_kernel<<<gg, 256>>>(sem,    LL,   0,    Wb, LL, p_bufA,  nullptr, p_bufB, 1);
    gemm4_kernel<<<gg, 256>>>(p_bufB, 4096, 1024, Wc, II, nullptr, nullptr, p_base, 0);
    gemm4_kernel<<<gg, 256>>>(cnn,    FF,   0,    Ca, FF, nullptr, nullptr, p_bufA, 0);
    gemm4_kernel<<<gg, 256>>>(sem,    LL,   0,    Cb, LL, p_bufA,  nullptr, p_bufB, 1);
    gemm4_kernel<<<gg, 256>>>(p_bufB, 4096, 1024, Cc, II, p_base,  bias,    p_base, 2);
    gemm4_kernel<<<gg, 256>>>(sem,    LL,   0,    Ub, LL, nullptr, nullptr, p_SH,   0);

    for (int t = 0; t < TT; t++) {
        // p0/p1 = h @ UaT (split-K halves)
        tcsplit_kernel<<<tg, 256, MM_SMEM>>>(p_h16, 1024, 0, p_UaT, p_p0, p_p1);
        // x16 = fp16((p0+p1) * SH)
        e1_kernel<<<BB * 4 * II / (256 * 4), 256>>>();
        // p0/p1 = x16 @ UcT (split-K halves)
        tcsplit_kernel<<<tg, 256, MM_SMEM>>>(p_x16, 4096, 1024, p_UcT, p_p0, p_p1);
        // gates: pre = p0+p1+base
        lstm_gate_kernel<<<(BB * HH + 255) / 256, 256>>>(t == TT - 1 ? (float*)d_out : nullptr);
    }
}